// round 3
// baseline (speedup 1.0000x reference)
#include <cuda_runtime.h>
#include <math.h>

#define T_TOK 4096
#define H     2048
#define IDIM  1024
#define NE    8
#define NTOT  12
#define CAP   4096
#define SCALE 1.5f

#define BM 64
#define BN 64
#define BK 16

// ---------------- scratch (static device globals; no runtime allocation) ----------------
__device__ int   g_cnt[NE];
__device__ int   g_tok[NE * CAP];
__device__ float g_wt [NE * CAP];
__device__ int   g_dst[NE * CAP];
__device__ float g_zw [T_TOK];
__device__ int   g_mask[T_TOK];
__device__ float g_act [(size_t)NE * CAP * IDIM];     // expert-grouped activations
__device__ float g_pair[(size_t)T_TOK * 2 * H];       // per (token,k) down output

// ---------------- router: one warp per token ----------------
__global__ void router_kernel(const float* __restrict__ x,
                              const float* __restrict__ cw,
                              const float* __restrict__ bias) {
    int warp = threadIdx.x >> 5;
    int lane = threadIdx.x & 31;
    int t = blockIdx.x * 4 + warp;
    if (t >= T_TOK) return;
    const float* xr = x + (size_t)t * H;

    float acc[NTOT];
#pragma unroll
    for (int e = 0; e < NTOT; e++) acc[e] = 0.f;
    for (int h = lane; h < H; h += 32) {
        float xv = xr[h];
#pragma unroll
        for (int e = 0; e < NTOT; e++) acc[e] += xv * cw[e * H + h];
    }
#pragma unroll
    for (int e = 0; e < NTOT; e++) {
#pragma unroll
        for (int off = 16; off; off >>= 1)
            acc[e] += __shfl_xor_sync(0xffffffffu, acc[e], off);
    }
    if (lane == 0) {
        float m = acc[0];
#pragma unroll
        for (int e = 1; e < NTOT; e++) m = fmaxf(m, acc[e]);
        float p[NTOT];
        float s = 0.f;
#pragma unroll
        for (int e = 0; e < NTOT; e++) { p[e] = expf(acc[e] - m); s += p[e]; }
        float inv = 1.f / s;
        float biased[NTOT];
#pragma unroll
        for (int e = 0; e < NTOT; e++) { p[e] *= inv; biased[e] = p[e] + bias[e]; }

        // top-2 of biased scores (lowest index wins ties, matching jax.lax.top_k)
        int i0 = 0;
#pragma unroll
        for (int e = 1; e < NTOT; e++) if (biased[e] > biased[i0]) i0 = e;
        int i1 = (i0 == 0) ? 1 : 0;
#pragma unroll
        for (int e = 0; e < NTOT; e++)
            if (e != i0 && biased[e] > biased[i1]) i1 = e;

        int sel[2] = { i0, i1 };
        float zw = 0.f;
        int mask = 0;
#pragma unroll
        for (int k = 0; k < 2; k++) {
            int e = sel[k];
            float w = p[e] * SCALE;       // weight uses UNBIASED prob
            if (e < NE) {
                int slot = atomicAdd(&g_cnt[e], 1);
                g_tok[e * CAP + slot] = t;
                g_wt [e * CAP + slot] = w;
                g_dst[e * CAP + slot] = t * 2 + k;
                mask |= (1 << k);
            } else {
                zw += w;                  // identity ("zero") expert
            }
        }
        g_zw[t]  = zw;
        g_mask[t] = mask;
    }
}

// ---------------- grouped gate+up GEMM with fused SiLU ----------------
// C tile: 64 tokens x 64 inter. K = H. Shared A tile feeds both gate and up.
__global__ __launch_bounds__(256) void gateup_kernel(const float* __restrict__ x,
                                                     const float* __restrict__ gw,
                                                     const float* __restrict__ uw) {
    int e = blockIdx.z;
    int cnt = g_cnt[e];
    int t0 = blockIdx.y * BM;
    if (t0 >= cnt) return;
    int i0 = blockIdx.x * BN;

    __shared__ float As[BK][BM + 1];
    __shared__ float Gs[BK][BN + 1];
    __shared__ float Us[BK][BN + 1];
    __shared__ int   toks[BM];

    int tid = threadIdx.x;
    if (tid < BM) {
        int s = t0 + tid;
        toks[tid] = g_tok[e * CAP + ((s < cnt) ? s : 0)];
    }
    __syncthreads();

    int lr = tid >> 2;            // 0..63 row within tile
    int lk = (tid & 3) * 4;       // 0,4,8,12 k-offset
    const float* arow = x + (size_t)toks[lr] * H;
    const float* grow = gw + (size_t)e * IDIM * H + (size_t)(i0 + lr) * H;
    const float* urow = uw + (size_t)e * IDIM * H + (size_t)(i0 + lr) * H;

    int tx = tid & 15;
    int ty = tid >> 4;
    float aG[4][4] = {};
    float aU[4][4] = {};

    for (int k0 = 0; k0 < H; k0 += BK) {
        float4 av = *(const float4*)(arow + k0 + lk);
        float4 gv = *(const float4*)(grow + k0 + lk);
        float4 uv = *(const float4*)(urow + k0 + lk);
        __syncthreads();
        As[lk + 0][lr] = av.x; As[lk + 1][lr] = av.y; As[lk + 2][lr] = av.z; As[lk + 3][lr] = av.w;
        Gs[lk + 0][lr] = gv.x; Gs[lk + 1][lr] = gv.y; Gs[lk + 2][lr] = gv.z; Gs[lk + 3][lr] = gv.w;
        Us[lk + 0][lr] = uv.x; Us[lk + 1][lr] = uv.y; Us[lk + 2][lr] = uv.z; Us[lk + 3][lr] = uv.w;
        __syncthreads();
#pragma unroll
        for (int kk = 0; kk < BK; kk++) {
            float a[4], g4[4], u4[4];
#pragma unroll
            for (int i = 0; i < 4; i++) a[i]  = As[kk][ty + i * 16];
#pragma unroll
            for (int j = 0; j < 4; j++) g4[j] = Gs[kk][tx + j * 16];
#pragma unroll
            for (int j = 0; j < 4; j++) u4[j] = Us[kk][tx + j * 16];
#pragma unroll
            for (int i = 0; i < 4; i++)
#pragma unroll
                for (int j = 0; j < 4; j++) {
                    aG[i][j] += a[i] * g4[j];
                    aU[i][j] += a[i] * u4[j];
                }
        }
    }

#pragma unroll
    for (int i = 0; i < 4; i++) {
        int srow = t0 + ty + i * 16;
        if (srow < cnt) {
            float* actRow = g_act + ((size_t)e * CAP + srow) * IDIM;
#pragma unroll
            for (int j = 0; j < 4; j++) {
                int col = i0 + tx + j * 16;
                float g = aG[i][j];
                float act = (g / (1.f + expf(-g))) * aU[i][j];  // silu(g) * u
                actRow[col] = act;
            }
        }
    }
}

// ---------------- grouped down GEMM, weight-scaled, scattered to pair buffer ----------------
// C tile: 64 slots x 64 h. K = IDIM.
__global__ __launch_bounds__(256) void down_kernel(const float* __restrict__ dw) {
    int e = blockIdx.z;
    int cnt = g_cnt[e];
    int s0 = blockIdx.y * BM;
    if (s0 >= cnt) return;
    int h0 = blockIdx.x * BN;

    __shared__ float As[BK][BM + 1];
    __shared__ float Bs[BK][BN + 1];
    __shared__ float wts[BM];
    __shared__ int   dsts[BM];

    int tid = threadIdx.x;
    if (tid < BM) {
        int s = s0 + tid;
        int cs = (s < cnt) ? s : 0;
        wts[tid]  = g_wt [e * CAP + cs];
        dsts[tid] = g_dst[e * CAP + cs];
    }
    __syncthreads();

    int lr = tid >> 2;
    int lk = (tid & 3) * 4;
    const float* arow = g_act + ((size_t)e * CAP + s0 + lr) * IDIM;  // rows >= cnt are garbage but guarded
    const float* brow = dw + (size_t)e * H * IDIM + (size_t)(h0 + lr) * IDIM;

    int tx = tid & 15;
    int ty = tid >> 4;
    float acc[4][4] = {};

    for (int k0 = 0; k0 < IDIM; k0 += BK) {
        float4 av = *(const float4*)(arow + k0 + lk);
        float4 bv = *(const float4*)(brow + k0 + lk);
        __syncthreads();
        As[lk + 0][lr] = av.x; As[lk + 1][lr] = av.y; As[lk + 2][lr] = av.z; As[lk + 3][lr] = av.w;
        Bs[lk + 0][lr] = bv.x; Bs[lk + 1][lr] = bv.y; Bs[lk + 2][lr] = bv.z; Bs[lk + 3][lr] = bv.w;
        __syncthreads();
#pragma unroll
        for (int kk = 0; kk < BK; kk++) {
            float a[4], b4[4];
#pragma unroll
            for (int i = 0; i < 4; i++) a[i]  = As[kk][ty + i * 16];
#pragma unroll
            for (int j = 0; j < 4; j++) b4[j] = Bs[kk][tx + j * 16];
#pragma unroll
            for (int i = 0; i < 4; i++)
#pragma unroll
                for (int j = 0; j < 4; j++) acc[i][j] += a[i] * b4[j];
        }
    }

#pragma unroll
    for (int i = 0; i < 4; i++) {
        int s = ty + i * 16;
        int srow = s0 + s;
        if (srow < cnt) {
            float w = wts[s];
            float* orow = g_pair + (size_t)dsts[s] * H;
#pragma unroll
            for (int j = 0; j < 4; j++) {
                orow[h0 + tx + j * 16] = acc[i][j] * w;
            }
        }
    }
}

// ---------------- combine: out = x*zero_w + valid pair contributions ----------------
__global__ void combine_kernel(const float* __restrict__ x, float* __restrict__ out) {
    int idx = blockIdx.x * blockDim.x + threadIdx.x;   // over T_TOK * H/4
    if (idx >= T_TOK * (H / 4)) return;
    int t  = idx / (H / 4);
    int h4 = idx % (H / 4);
    float4 xv = ((const float4*)x)[idx];
    float zw = g_zw[t];
    int mask = g_mask[t];
    float4 r;
    r.x = xv.x * zw; r.y = xv.y * zw; r.z = xv.z * zw; r.w = xv.w * zw;
    if (mask & 1) {
        float4 p = ((const float4*)(g_pair + (size_t)(t * 2) * H))[h4];
        r.x += p.x; r.y += p.y; r.z += p.z; r.w += p.w;
    }
    if (mask & 2) {
        float4 p = ((const float4*)(g_pair + (size_t)(t * 2 + 1) * H))[h4];
        r.x += p.x; r.y += p.y; r.z += p.z; r.w += p.w;
    }
    ((float4*)out)[idx] = r;
}

// ---------------- launch ----------------
extern "C" void kernel_launch(void* const* d_in, const int* in_sizes, int n_in,
                              void* d_out, int out_size) {
    const float* x    = (const float*)d_in[0];
    const float* cw   = (const float*)d_in[1];
    const float* bias = (const float*)d_in[2];
    const float* gw   = (const float*)d_in[3];
    const float* uw   = (const float*)d_in[4];
    const float* dw   = (const float*)d_in[5];
    float* out = (float*)d_out;

    void* cntAddr = nullptr;
    cudaGetSymbolAddress(&cntAddr, g_cnt);
    cudaMemsetAsync(cntAddr, 0, NE * sizeof(int));

    router_kernel<<<T_TOK / 4, 128>>>(x, cw, bias);

    dim3 gb(IDIM / BN, T_TOK / BM, NE);
    gateup_kernel<<<gb, 256>>>(x, gw, uw);

    dim3 gd(H / BN, T_TOK / BM, NE);
    down_kernel<<<gd, 256>>>(dw);

    int n4 = T_TOK * (H / 4);
    combine_kernel<<<(n4 + 255) / 256, 256>>>(x, out);
}

// round 5
// speedup vs baseline: 2.6954x; 2.6954x over previous
#include <cuda_runtime.h>
#include <math.h>
#include <stdint.h>

#define T_TOK 4096
#define H     2048
#define IDIM  1024
#define NE    8
#define NTOT  12
#define CAP   4096
#define SCALE 1.5f

// ---------------- scratch (static device globals; no runtime allocation) ----------------
__device__ int   g_cnt[NE];
__device__ int   g_tok[NE * CAP];
__device__ float g_wt [NE * CAP];
__device__ int   g_dst[NE * CAP];
__device__ float g_zw [T_TOK];
__device__ int   g_mask[T_TOK];
__device__ float g_act [(size_t)NE * CAP * IDIM];     // expert-grouped activations
__device__ float g_pair[(size_t)T_TOK * 2 * H];       // per (token,k) down output

// ---------------- helpers ----------------
__device__ __forceinline__ uint32_t f2tf32(float f) {
    uint32_t r;
    asm("cvt.rna.tf32.f32 %0, %1;" : "=r"(r) : "f"(f));
    return r;
}

__device__ __forceinline__ void mma_tf32(float c[4],
                                         uint32_t a0, uint32_t a1, uint32_t a2, uint32_t a3,
                                         uint32_t b0, uint32_t b1) {
    asm volatile(
        "mma.sync.aligned.m16n8k8.row.col.f32.tf32.tf32.f32 "
        "{%0,%1,%2,%3}, {%4,%5,%6,%7}, {%8,%9}, {%0,%1,%2,%3};\n"
        : "+f"(c[0]), "+f"(c[1]), "+f"(c[2]), "+f"(c[3])
        : "r"(a0), "r"(a1), "r"(a2), "r"(a3), "r"(b0), "r"(b1));
}

// ---------------- router: one warp per token ----------------
__global__ void router_kernel(const float* __restrict__ x,
                              const float* __restrict__ cw,
                              const float* __restrict__ bias) {
    int warp = threadIdx.x >> 5;
    int lane = threadIdx.x & 31;
    int t = blockIdx.x * 4 + warp;
    if (t >= T_TOK) return;
    const float* xr = x + (size_t)t * H;

    float acc[NTOT];
#pragma unroll
    for (int e = 0; e < NTOT; e++) acc[e] = 0.f;
    for (int h = lane; h < H; h += 32) {
        float xv = xr[h];
#pragma unroll
        for (int e = 0; e < NTOT; e++) acc[e] += xv * __ldg(&cw[e * H + h]);
    }
#pragma unroll
    for (int e = 0; e < NTOT; e++) {
#pragma unroll
        for (int off = 16; off; off >>= 1)
            acc[e] += __shfl_xor_sync(0xffffffffu, acc[e], off);
    }
    if (lane == 0) {
        float m = acc[0];
#pragma unroll
        for (int e = 1; e < NTOT; e++) m = fmaxf(m, acc[e]);
        float p[NTOT];
        float s = 0.f;
#pragma unroll
        for (int e = 0; e < NTOT; e++) { p[e] = expf(acc[e] - m); s += p[e]; }
        float inv = 1.f / s;
        float biased[NTOT];
#pragma unroll
        for (int e = 0; e < NTOT; e++) { p[e] *= inv; biased[e] = p[e] + bias[e]; }

        // top-2 of biased scores (lowest index wins ties, matching jax.lax.top_k)
        int i0 = 0;
#pragma unroll
        for (int e = 1; e < NTOT; e++) if (biased[e] > biased[i0]) i0 = e;
        int i1 = (i0 == 0) ? 1 : 0;
#pragma unroll
        for (int e = 0; e < NTOT; e++)
            if (e != i0 && biased[e] > biased[i1]) i1 = e;

        int sel[2] = { i0, i1 };
        float zw = 0.f;
        int mask = 0;
#pragma unroll
        for (int k = 0; k < 2; k++) {
            int e = sel[k];
            float w = p[e] * SCALE;       // weight uses UNBIASED prob
            if (e < NE) {
                int slot = atomicAdd(&g_cnt[e], 1);
                g_tok[e * CAP + slot] = t;
                g_wt [e * CAP + slot] = w;
                g_dst[e * CAP + slot] = t * 2 + k;
                mask |= (1 << k);
            } else {
                zw += w;
            }
        }
        g_zw[t]  = zw;
        g_mask[t] = mask;
    }
}

// ---------------- grouped gate+up tf32 tensor-core GEMM with fused SiLU ----------------
// Block tile: 64 slots x 128 inter, BK=32. 8 warps (2x4). Warp tile 32x32 for
// BOTH gate and up (shared A fragments).
#define GU_BM 64
#define GU_BN 128
#define GU_BK 32
#define SMS 36   // smem k-stride (32 + 4 pad)

__global__ __launch_bounds__(256, 1) void gateup_kernel(const float* __restrict__ x,
                                                        const float* __restrict__ gw,
                                                        const float* __restrict__ uw) {
    int e = blockIdx.z;
    int cnt = g_cnt[e];
    int t0 = blockIdx.y * GU_BM;
    if (t0 >= cnt) return;
    int i0 = blockIdx.x * GU_BN;

    __shared__ float As[GU_BM][SMS];
    __shared__ float Gs[GU_BN][SMS];
    __shared__ float Us[GU_BN][SMS];
    __shared__ int   toks[GU_BM];

    int tid  = threadIdx.x;
    int lane = tid & 31;
    int warp = tid >> 5;
    int wm = warp >> 2;       // 0..1
    int wn = warp & 3;        // 0..3
    int g = lane >> 2;        // groupID 0..7
    int tg = lane & 3;        // thread in group 0..3

    if (tid < GU_BM) {
        int s = t0 + tid;
        toks[tid] = g_tok[e * CAP + ((s < cnt) ? s : 0)];
    }
    __syncthreads();

    int r8 = tid >> 3;          // 0..31
    int c4 = (tid & 7) * 4;     // 0..28

    const float* ar0 = x + (size_t)toks[r8] * H + c4;
    const float* ar1 = x + (size_t)toks[r8 + 32] * H + c4;
    const float* gbase = gw + (size_t)e * IDIM * H + (size_t)i0 * H;
    const float* ubase = uw + (size_t)e * IDIM * H + (size_t)i0 * H;

    float cg[2][4][4] = {};
    float cu[2][4][4] = {};

    for (int k0 = 0; k0 < H; k0 += GU_BK) {
        // prefetch globals
        float4 va0 = *(const float4*)(ar0 + k0);
        float4 va1 = *(const float4*)(ar1 + k0);
        float4 vg[4], vu[4];
#pragma unroll
        for (int p = 0; p < 4; p++) {
            int n = r8 + p * 32;
            vg[p] = __ldg((const float4*)(gbase + (size_t)n * H + k0 + c4));
            vu[p] = __ldg((const float4*)(ubase + (size_t)n * H + k0 + c4));
        }
        __syncthreads();
        {
            uint4 t;
            t.x = f2tf32(va0.x); t.y = f2tf32(va0.y); t.z = f2tf32(va0.z); t.w = f2tf32(va0.w);
            *(uint4*)&As[r8][c4] = t;
            t.x = f2tf32(va1.x); t.y = f2tf32(va1.y); t.z = f2tf32(va1.z); t.w = f2tf32(va1.w);
            *(uint4*)&As[r8 + 32][c4] = t;
#pragma unroll
            for (int p = 0; p < 4; p++) {
                t.x = f2tf32(vg[p].x); t.y = f2tf32(vg[p].y); t.z = f2tf32(vg[p].z); t.w = f2tf32(vg[p].w);
                *(uint4*)&Gs[r8 + p * 32][c4] = t;
                t.x = f2tf32(vu[p].x); t.y = f2tf32(vu[p].y); t.z = f2tf32(vu[p].z); t.w = f2tf32(vu[p].w);
                *(uint4*)&Us[r8 + p * 32][c4] = t;
            }
        }
        __syncthreads();

#pragma unroll
        for (int ks = 0; ks < GU_BK / 8; ks++) {
            int kb = ks * 8;
            uint32_t a[2][4];
#pragma unroll
            for (int mi = 0; mi < 2; mi++) {
                int rb = wm * 32 + mi * 16;
                a[mi][0] = *(const uint32_t*)&As[rb + g    ][kb + tg];
                a[mi][1] = *(const uint32_t*)&As[rb + g + 8][kb + tg];
                a[mi][2] = *(const uint32_t*)&As[rb + g    ][kb + tg + 4];
                a[mi][3] = *(const uint32_t*)&As[rb + g + 8][kb + tg + 4];
            }
#pragma unroll
            for (int ni = 0; ni < 4; ni++) {
                int nb = wn * 32 + ni * 8 + g;
                uint32_t bg0 = *(const uint32_t*)&Gs[nb][kb + tg];
                uint32_t bg1 = *(const uint32_t*)&Gs[nb][kb + tg + 4];
                uint32_t bu0 = *(const uint32_t*)&Us[nb][kb + tg];
                uint32_t bu1 = *(const uint32_t*)&Us[nb][kb + tg + 4];
#pragma unroll
                for (int mi = 0; mi < 2; mi++) {
                    mma_tf32(cg[mi][ni], a[mi][0], a[mi][1], a[mi][2], a[mi][3], bg0, bg1);
                    mma_tf32(cu[mi][ni], a[mi][0], a[mi][1], a[mi][2], a[mi][3], bu0, bu1);
                }
            }
        }
    }

    // epilogue: act = silu(gate) * up
#pragma unroll
    for (int mi = 0; mi < 2; mi++) {
        int r0 = wm * 32 + mi * 16 + g;
        int srow0 = t0 + r0;
        int srow1 = srow0 + 8;
        float* row0 = g_act + ((size_t)e * CAP + srow0) * IDIM;
        float* row1 = g_act + ((size_t)e * CAP + srow1) * IDIM;
#pragma unroll
        for (int ni = 0; ni < 4; ni++) {
            int col = i0 + wn * 32 + ni * 8 + tg * 2;
            if (srow0 < cnt) {
                float g0 = cg[mi][ni][0], g1 = cg[mi][ni][1];
                float2 v;
                v.x = (g0 / (1.f + expf(-g0))) * cu[mi][ni][0];
                v.y = (g1 / (1.f + expf(-g1))) * cu[mi][ni][1];
                *(float2*)(row0 + col) = v;
            }
            if (srow1 < cnt) {
                float g2 = cg[mi][ni][2], g3 = cg[mi][ni][3];
                float2 v;
                v.x = (g2 / (1.f + expf(-g2))) * cu[mi][ni][2];
                v.y = (g3 / (1.f + expf(-g3))) * cu[mi][ni][3];
                *(float2*)(row1 + col) = v;
            }
        }
    }
}

// ---------------- grouped down tf32 GEMM, weight-scaled, scattered ----------------
// Block tile: 64 slots x 256 H, BK=32. 8 warps (2x4). Warp tile 32x64.
#define DN_BM 64
#define DN_BN 256
#define DN_BK 32

__global__ __launch_bounds__(256, 1) void down_kernel(const float* __restrict__ dw) {
    int e = blockIdx.z;
    int cnt = g_cnt[e];
    int s0 = blockIdx.y * DN_BM;
    if (s0 >= cnt) return;
    int h0 = blockIdx.x * DN_BN;

    __shared__ float As[DN_BM][SMS];
    __shared__ float Bs[DN_BN][SMS];
    __shared__ float wts[DN_BM];
    __shared__ int   dsts[DN_BM];

    int tid  = threadIdx.x;
    int lane = tid & 31;
    int warp = tid >> 5;
    int wm = warp >> 2;
    int wn = warp & 3;
    int g = lane >> 2;
    int tg = lane & 3;

    if (tid < DN_BM) {
        int s = s0 + tid;
        int cs = (s < cnt) ? s : 0;
        wts[tid]  = g_wt [e * CAP + cs];
        dsts[tid] = g_dst[e * CAP + cs];
    }
    __syncthreads();

    int r8 = tid >> 3;
    int c4 = (tid & 7) * 4;

    const float* ar0 = g_act + ((size_t)e * CAP + s0 + r8) * IDIM + c4;
    const float* ar1 = ar0 + (size_t)32 * IDIM;
    const float* bbase = dw + (size_t)e * H * IDIM + (size_t)h0 * IDIM;

    float acc[2][8][4] = {};

    for (int k0 = 0; k0 < IDIM; k0 += DN_BK) {
        float4 va0 = *(const float4*)(ar0 + k0);
        float4 va1 = *(const float4*)(ar1 + k0);
        float4 vb[8];
#pragma unroll
        for (int p = 0; p < 8; p++) {
            int n = r8 + p * 32;
            vb[p] = __ldg((const float4*)(bbase + (size_t)n * IDIM + k0 + c4));
        }
        __syncthreads();
        {
            uint4 t;
            t.x = f2tf32(va0.x); t.y = f2tf32(va0.y); t.z = f2tf32(va0.z); t.w = f2tf32(va0.w);
            *(uint4*)&As[r8][c4] = t;
            t.x = f2tf32(va1.x); t.y = f2tf32(va1.y); t.z = f2tf32(va1.z); t.w = f2tf32(va1.w);
            *(uint4*)&As[r8 + 32][c4] = t;
#pragma unroll
            for (int p = 0; p < 8; p++) {
                t.x = f2tf32(vb[p].x); t.y = f2tf32(vb[p].y); t.z = f2tf32(vb[p].z); t.w = f2tf32(vb[p].w);
                *(uint4*)&Bs[r8 + p * 32][c4] = t;
            }
        }
        __syncthreads();

#pragma unroll
        for (int ks = 0; ks < DN_BK / 8; ks++) {
            int kb = ks * 8;
            uint32_t a[2][4];
#pragma unroll
            for (int mi = 0; mi < 2; mi++) {
                int rb = wm * 32 + mi * 16;
                a[mi][0] = *(const uint32_t*)&As[rb + g    ][kb + tg];
                a[mi][1] = *(const uint32_t*)&As[rb + g + 8][kb + tg];
                a[mi][2] = *(const uint32_t*)&As[rb + g    ][kb + tg + 4];
                a[mi][3] = *(const uint32_t*)&As[rb + g + 8][kb + tg + 4];
            }
#pragma unroll
            for (int ni = 0; ni < 8; ni++) {
                int nb = wn * 64 + ni * 8 + g;
                uint32_t b0 = *(const uint32_t*)&Bs[nb][kb + tg];
                uint32_t b1 = *(const uint32_t*)&Bs[nb][kb + tg + 4];
#pragma unroll
                for (int mi = 0; mi < 2; mi++)
                    mma_tf32(acc[mi][ni], a[mi][0], a[mi][1], a[mi][2], a[mi][3], b0, b1);
            }
        }
    }

#pragma unroll
    for (int mi = 0; mi < 2; mi++) {
        int r0 = wm * 32 + mi * 16 + g;
        int r1 = r0 + 8;
        int srow0 = s0 + r0;
        int srow1 = s0 + r1;
        float w0 = wts[r0], w1 = wts[r1];
        float* o0 = g_pair + (size_t)dsts[r0] * H + h0;
        float* o1 = g_pair + (size_t)dsts[r1] * H + h0;
#pragma unroll
        for (int ni = 0; ni < 8; ni++) {
            int col = wn * 64 + ni * 8 + tg * 2;
            if (srow0 < cnt) {
                float2 v = { acc[mi][ni][0] * w0, acc[mi][ni][1] * w0 };
                *(float2*)(o0 + col) = v;
            }
            if (srow1 < cnt) {
                float2 v = { acc[mi][ni][2] * w1, acc[mi][ni][3] * w1 };
                *(float2*)(o1 + col) = v;
            }
        }
    }
}

// ---------------- combine: out = x*zero_w + valid pair contributions ----------------
__global__ void combine_kernel(const float* __restrict__ x, float* __restrict__ out) {
    int idx = blockIdx.x * blockDim.x + threadIdx.x;
    if (idx >= T_TOK * (H / 4)) return;
    int t  = idx / (H / 4);
    int h4 = idx % (H / 4);
    float4 xv = ((const float4*)x)[idx];
    float zw = g_zw[t];
    int mask = g_mask[t];
    float4 r;
    r.x = xv.x * zw; r.y = xv.y * zw; r.z = xv.z * zw; r.w = xv.w * zw;
    if (mask & 1) {
        float4 p = ((const float4*)(g_pair + (size_t)(t * 2) * H))[h4];
        r.x += p.x; r.y += p.y; r.z += p.z; r.w += p.w;
    }
    if (mask & 2) {
        float4 p = ((const float4*)(g_pair + (size_t)(t * 2 + 1) * H))[h4];
        r.x += p.x; r.y += p.y; r.z += p.z; r.w += p.w;
    }
    ((float4*)out)[idx] = r;
}

// ---------------- launch ----------------
extern "C" void kernel_launch(void* const* d_in, const int* in_sizes, int n_in,
                              void* d_out, int out_size) {
    const float* x    = (const float*)d_in[0];
    const float* cw   = (const float*)d_in[1];
    const float* bias = (const float*)d_in[2];
    const float* gw   = (const float*)d_in[3];
    const float* uw   = (const float*)d_in[4];
    const float* dw   = (const float*)d_in[5];
    float* out = (float*)d_out;

    void* cntAddr = nullptr;
    cudaGetSymbolAddress(&cntAddr, g_cnt);
    cudaMemsetAsync(cntAddr, 0, NE * sizeof(int));

    router_kernel<<<T_TOK / 4, 128>>>(x, cw, bias);

    dim3 gb(IDIM / GU_BN, T_TOK / GU_BM, NE);
    gateup_kernel<<<gb, 256>>>(x, gw, uw);

    dim3 gd(H / DN_BN, T_TOK / DN_BM, NE);
    down_kernel<<<gd, 256>>>(dw);

    int n4 = T_TOK * (H / 4);
    combine_kernel<<<(n4 + 255) / 256, 256>>>(x, out);
}

// round 6
// speedup vs baseline: 3.2040x; 1.1887x over previous
#include <cuda_runtime.h>
#include <math.h>
#include <stdint.h>

#define T_TOK 4096
#define H     2048
#define IDIM  1024
#define NE    8
#define NTOT  12
#define CAP   4096
#define SCALE 1.5f

// ---------------- scratch (static device globals; no runtime allocation) ----------------
__device__ int   g_cnt[NE];
__device__ int   g_tok[NE * CAP];
__device__ float g_wt [NE * CAP];
__device__ int   g_dst[NE * CAP];
__device__ float g_zw [T_TOK];
__device__ int   g_mask[T_TOK];
__device__ float g_act [(size_t)NE * CAP * IDIM];     // expert-grouped activations
__device__ float g_pair[(size_t)T_TOK * 2 * H];       // per (token,k) down output

// ---------------- helpers ----------------
__device__ __forceinline__ uint32_t f2tf32(float f) {
    uint32_t r;
    asm("cvt.rna.tf32.f32 %0, %1;" : "=r"(r) : "f"(f));
    return r;
}

__device__ __forceinline__ void mma_tf32(float c[4],
                                         uint32_t a0, uint32_t a1, uint32_t a2, uint32_t a3,
                                         uint32_t b0, uint32_t b1) {
    asm volatile(
        "mma.sync.aligned.m16n8k8.row.col.f32.tf32.tf32.f32 "
        "{%0,%1,%2,%3}, {%4,%5,%6,%7}, {%8,%9}, {%0,%1,%2,%3};\n"
        : "+f"(c[0]), "+f"(c[1]), "+f"(c[2]), "+f"(c[3])
        : "r"(a0), "r"(a1), "r"(a2), "r"(a3), "r"(b0), "r"(b1));
}

// ---------------- router: one warp per token ----------------
__global__ void router_kernel(const float* __restrict__ x,
                              const float* __restrict__ cw,
                              const float* __restrict__ bias) {
    int warp = threadIdx.x >> 5;
    int lane = threadIdx.x & 31;
    int t = blockIdx.x * 4 + warp;
    if (t >= T_TOK) return;
    const float* xr = x + (size_t)t * H;

    float acc[NTOT];
#pragma unroll
    for (int e = 0; e < NTOT; e++) acc[e] = 0.f;
    for (int h = lane; h < H; h += 32) {
        float xv = xr[h];
#pragma unroll
        for (int e = 0; e < NTOT; e++) acc[e] += xv * __ldg(&cw[e * H + h]);
    }
#pragma unroll
    for (int e = 0; e < NTOT; e++) {
#pragma unroll
        for (int off = 16; off; off >>= 1)
            acc[e] += __shfl_xor_sync(0xffffffffu, acc[e], off);
    }
    if (lane == 0) {
        float m = acc[0];
#pragma unroll
        for (int e = 1; e < NTOT; e++) m = fmaxf(m, acc[e]);
        float p[NTOT];
        float s = 0.f;
#pragma unroll
        for (int e = 0; e < NTOT; e++) { p[e] = expf(acc[e] - m); s += p[e]; }
        float inv = 1.f / s;
        float biased[NTOT];
#pragma unroll
        for (int e = 0; e < NTOT; e++) { p[e] *= inv; biased[e] = p[e] + bias[e]; }

        // top-2 of biased scores (lowest index wins ties, matching jax.lax.top_k)
        int i0 = 0;
#pragma unroll
        for (int e = 1; e < NTOT; e++) if (biased[e] > biased[i0]) i0 = e;
        int i1 = (i0 == 0) ? 1 : 0;
#pragma unroll
        for (int e = 0; e < NTOT; e++)
            if (e != i0 && biased[e] > biased[i1]) i1 = e;

        int sel[2] = { i0, i1 };
        float zw = 0.f;
        int mask = 0;
#pragma unroll
        for (int k = 0; k < 2; k++) {
            int e = sel[k];
            float w = p[e] * SCALE;       // weight uses UNBIASED prob
            if (e < NE) {
                int slot = atomicAdd(&g_cnt[e], 1);
                g_tok[e * CAP + slot] = t;
                g_wt [e * CAP + slot] = w;
                g_dst[e * CAP + slot] = t * 2 + k;
                mask |= (1 << k);
            } else {
                zw += w;
            }
        }
        g_zw[t]  = zw;
        g_mask[t] = mask;
    }
}

// ---------------- grouped gate+up tf32 GEMM with fused SiLU ----------------
// Block tile: 128 slots x 64 inter, BK=32. 8 warps (4x2). Warp tile 32x32 for
// BOTH gate and up (shared A fragments). Global loads software-pipelined.
#define GU_BM 128
#define GU_BN 64
#define GU_BK 32
#define SMS 36   // smem k-stride (32 + 4 pad)

__global__ __launch_bounds__(256, 1) void gateup_kernel(const float* __restrict__ x,
                                                        const float* __restrict__ gw,
                                                        const float* __restrict__ uw) {
    int e = blockIdx.z;
    int cnt = g_cnt[e];
    int t0 = blockIdx.y * GU_BM;
    if (t0 >= cnt) return;
    int i0 = blockIdx.x * GU_BN;

    __shared__ float As[GU_BM][SMS];
    __shared__ float Gs[GU_BN][SMS];
    __shared__ float Us[GU_BN][SMS];
    __shared__ int   toks[GU_BM];

    int tid  = threadIdx.x;
    int lane = tid & 31;
    int warp = tid >> 5;
    int wm = warp >> 1;       // 0..3
    int wn = warp & 1;        // 0..1
    int g = lane >> 2;        // 0..7
    int tg = lane & 3;        // 0..3

    if (tid < GU_BM) {
        int s = t0 + tid;
        toks[tid] = g_tok[e * CAP + ((s < cnt) ? s : 0)];
    }
    __syncthreads();

    int r8 = tid >> 3;          // 0..31
    int c4 = (tid & 7) * 4;     // 0..28

    const float* arow[4];
#pragma unroll
    for (int p = 0; p < 4; p++)
        arow[p] = x + (size_t)toks[r8 + p * 32] * H + c4;
    const float* gbase = gw + (size_t)e * IDIM * H + (size_t)i0 * H;
    const float* ubase = uw + (size_t)e * IDIM * H + (size_t)i0 * H;

    float cg[2][4][4] = {};
    float cu[2][4][4] = {};

    // prefetch first k-chunk
    float4 va[4], vg[2], vu[2];
#pragma unroll
    for (int p = 0; p < 4; p++) va[p] = *(const float4*)(arow[p]);
#pragma unroll
    for (int p = 0; p < 2; p++) {
        int n = r8 + p * 32;
        vg[p] = __ldg((const float4*)(gbase + (size_t)n * H + c4));
        vu[p] = __ldg((const float4*)(ubase + (size_t)n * H + c4));
    }

    for (int k0 = 0; k0 < H; k0 += GU_BK) {
        __syncthreads();   // previous MMA reads done
        {
            uint4 t;
#pragma unroll
            for (int p = 0; p < 4; p++) {
                t.x = f2tf32(va[p].x); t.y = f2tf32(va[p].y); t.z = f2tf32(va[p].z); t.w = f2tf32(va[p].w);
                *(uint4*)&As[r8 + p * 32][c4] = t;
            }
#pragma unroll
            for (int p = 0; p < 2; p++) {
                t.x = f2tf32(vg[p].x); t.y = f2tf32(vg[p].y); t.z = f2tf32(vg[p].z); t.w = f2tf32(vg[p].w);
                *(uint4*)&Gs[r8 + p * 32][c4] = t;
                t.x = f2tf32(vu[p].x); t.y = f2tf32(vu[p].y); t.z = f2tf32(vu[p].z); t.w = f2tf32(vu[p].w);
                *(uint4*)&Us[r8 + p * 32][c4] = t;
            }
        }
        __syncthreads();

        // prefetch next k-chunk (overlaps MMA below)
        int kn = k0 + GU_BK;
        if (kn < H) {
#pragma unroll
            for (int p = 0; p < 4; p++) va[p] = *(const float4*)(arow[p] + kn);
#pragma unroll
            for (int p = 0; p < 2; p++) {
                int n = r8 + p * 32;
                vg[p] = __ldg((const float4*)(gbase + (size_t)n * H + kn + c4));
                vu[p] = __ldg((const float4*)(ubase + (size_t)n * H + kn + c4));
            }
        }

#pragma unroll
        for (int ks = 0; ks < GU_BK / 8; ks++) {
            int kb = ks * 8;
            uint32_t a[2][4];
#pragma unroll
            for (int mi = 0; mi < 2; mi++) {
                int rb = wm * 32 + mi * 16;
                a[mi][0] = *(const uint32_t*)&As[rb + g    ][kb + tg];
                a[mi][1] = *(const uint32_t*)&As[rb + g + 8][kb + tg];
                a[mi][2] = *(const uint32_t*)&As[rb + g    ][kb + tg + 4];
                a[mi][3] = *(const uint32_t*)&As[rb + g + 8][kb + tg + 4];
            }
#pragma unroll
            for (int ni = 0; ni < 4; ni++) {
                int nb = wn * 32 + ni * 8 + g;
                uint32_t bg0 = *(const uint32_t*)&Gs[nb][kb + tg];
                uint32_t bg1 = *(const uint32_t*)&Gs[nb][kb + tg + 4];
                uint32_t bu0 = *(const uint32_t*)&Us[nb][kb + tg];
                uint32_t bu1 = *(const uint32_t*)&Us[nb][kb + tg + 4];
#pragma unroll
                for (int mi = 0; mi < 2; mi++) {
                    mma_tf32(cg[mi][ni], a[mi][0], a[mi][1], a[mi][2], a[mi][3], bg0, bg1);
                    mma_tf32(cu[mi][ni], a[mi][0], a[mi][1], a[mi][2], a[mi][3], bu0, bu1);
                }
            }
        }
    }

    // epilogue: act = silu(gate) * up
#pragma unroll
    for (int mi = 0; mi < 2; mi++) {
        int r0 = wm * 32 + mi * 16 + g;
        int srow0 = t0 + r0;
        int srow1 = srow0 + 8;
        float* row0 = g_act + ((size_t)e * CAP + srow0) * IDIM;
        float* row1 = g_act + ((size_t)e * CAP + srow1) * IDIM;
#pragma unroll
        for (int ni = 0; ni < 4; ni++) {
            int col = i0 + wn * 32 + ni * 8 + tg * 2;
            if (srow0 < cnt) {
                float g0 = cg[mi][ni][0], g1 = cg[mi][ni][1];
                float2 v;
                v.x = (g0 / (1.f + expf(-g0))) * cu[mi][ni][0];
                v.y = (g1 / (1.f + expf(-g1))) * cu[mi][ni][1];
                *(float2*)(row0 + col) = v;
            }
            if (srow1 < cnt) {
                float g2 = cg[mi][ni][2], g3 = cg[mi][ni][3];
                float2 v;
                v.x = (g2 / (1.f + expf(-g2))) * cu[mi][ni][2];
                v.y = (g3 / (1.f + expf(-g3))) * cu[mi][ni][3];
                *(float2*)(row1 + col) = v;
            }
        }
    }
}

// ---------------- grouped down tf32 GEMM, weight-scaled, scattered ----------------
// Block tile: 128 slots x 128 H, BK=32. 8 warps (4x2). Warp tile 32x64.
#define DN_BM 128
#define DN_BN 128
#define DN_BK 32

__global__ __launch_bounds__(256, 1) void down_kernel(const float* __restrict__ dw) {
    int e = blockIdx.z;
    int cnt = g_cnt[e];
    int s0 = blockIdx.y * DN_BM;
    if (s0 >= cnt) return;
    int h0 = blockIdx.x * DN_BN;

    __shared__ float As[DN_BM][SMS];
    __shared__ float Bs[DN_BN][SMS];
    __shared__ float wts[DN_BM];
    __shared__ int   dsts[DN_BM];

    int tid  = threadIdx.x;
    int lane = tid & 31;
    int warp = tid >> 5;
    int wm = warp >> 1;      // 0..3
    int wn = warp & 1;       // 0..1
    int g = lane >> 2;
    int tg = lane & 3;

    if (tid < DN_BM) {
        int s = s0 + tid;
        int cs = (s < cnt) ? s : 0;
        wts[tid]  = g_wt [e * CAP + cs];
        dsts[tid] = g_dst[e * CAP + cs];
    }
    __syncthreads();

    int r8 = tid >> 3;
    int c4 = (tid & 7) * 4;

    const float* arow[4];
#pragma unroll
    for (int p = 0; p < 4; p++)
        arow[p] = g_act + ((size_t)e * CAP + s0 + r8 + p * 32) * IDIM + c4;
    const float* bbase = dw + (size_t)e * H * IDIM + (size_t)h0 * IDIM;

    float acc[2][8][4] = {};

    float4 va[4], vb[4];
#pragma unroll
    for (int p = 0; p < 4; p++) va[p] = *(const float4*)(arow[p]);
#pragma unroll
    for (int p = 0; p < 4; p++)
        vb[p] = __ldg((const float4*)(bbase + (size_t)(r8 + p * 32) * IDIM + c4));

    for (int k0 = 0; k0 < IDIM; k0 += DN_BK) {
        __syncthreads();
        {
            uint4 t;
#pragma unroll
            for (int p = 0; p < 4; p++) {
                t.x = f2tf32(va[p].x); t.y = f2tf32(va[p].y); t.z = f2tf32(va[p].z); t.w = f2tf32(va[p].w);
                *(uint4*)&As[r8 + p * 32][c4] = t;
            }
#pragma unroll
            for (int p = 0; p < 4; p++) {
                t.x = f2tf32(vb[p].x); t.y = f2tf32(vb[p].y); t.z = f2tf32(vb[p].z); t.w = f2tf32(vb[p].w);
                *(uint4*)&Bs[r8 + p * 32][c4] = t;
            }
        }
        __syncthreads();

        int kn = k0 + DN_BK;
        if (kn < IDIM) {
#pragma unroll
            for (int p = 0; p < 4; p++) va[p] = *(const float4*)(arow[p] + kn);
#pragma unroll
            for (int p = 0; p < 4; p++)
                vb[p] = __ldg((const float4*)(bbase + (size_t)(r8 + p * 32) * IDIM + kn + c4));
        }

#pragma unroll
        for (int ks = 0; ks < DN_BK / 8; ks++) {
            int kb = ks * 8;
            uint32_t a[2][4];
#pragma unroll
            for (int mi = 0; mi < 2; mi++) {
                int rb = wm * 32 + mi * 16;
                a[mi][0] = *(const uint32_t*)&As[rb + g    ][kb + tg];
                a[mi][1] = *(const uint32_t*)&As[rb + g + 8][kb + tg];
                a[mi][2] = *(const uint32_t*)&As[rb + g    ][kb + tg + 4];
                a[mi][3] = *(const uint32_t*)&As[rb + g + 8][kb + tg + 4];
            }
#pragma unroll
            for (int ni = 0; ni < 8; ni++) {
                int nb = wn * 64 + ni * 8 + g;
                uint32_t b0 = *(const uint32_t*)&Bs[nb][kb + tg];
                uint32_t b1 = *(const uint32_t*)&Bs[nb][kb + tg + 4];
#pragma unroll
                for (int mi = 0; mi < 2; mi++)
                    mma_tf32(acc[mi][ni], a[mi][0], a[mi][1], a[mi][2], a[mi][3], b0, b1);
            }
        }
    }

#pragma unroll
    for (int mi = 0; mi < 2; mi++) {
        int r0 = wm * 32 + mi * 16 + g;
        int r1 = r0 + 8;
        int srow0 = s0 + r0;
        int srow1 = s0 + r1;
        float w0 = wts[r0], w1 = wts[r1];
        float* o0 = g_pair + (size_t)dsts[r0] * H + h0;
        float* o1 = g_pair + (size_t)dsts[r1] * H + h0;
#pragma unroll
        for (int ni = 0; ni < 8; ni++) {
            int col = wn * 64 + ni * 8 + tg * 2;
            if (srow0 < cnt) {
                float2 v = { acc[mi][ni][0] * w0, acc[mi][ni][1] * w0 };
                *(float2*)(o0 + col) = v;
            }
            if (srow1 < cnt) {
                float2 v = { acc[mi][ni][2] * w1, acc[mi][ni][3] * w1 };
                *(float2*)(o1 + col) = v;
            }
        }
    }
}

// ---------------- combine: out = x*zero_w + valid pair contributions ----------------
__global__ void combine_kernel(const float* __restrict__ x, float* __restrict__ out) {
    int idx = blockIdx.x * blockDim.x + threadIdx.x;
    if (idx >= T_TOK * (H / 4)) return;
    int t  = idx / (H / 4);
    int h4 = idx % (H / 4);
    float4 xv = ((const float4*)x)[idx];
    float zw = g_zw[t];
    int mask = g_mask[t];
    float4 r;
    r.x = xv.x * zw; r.y = xv.y * zw; r.z = xv.z * zw; r.w = xv.w * zw;
    if (mask & 1) {
        float4 p = ((const float4*)(g_pair + (size_t)(t * 2) * H))[h4];
        r.x += p.x; r.y += p.y; r.z += p.z; r.w += p.w;
    }
    if (mask & 2) {
        float4 p = ((const float4*)(g_pair + (size_t)(t * 2 + 1) * H))[h4];
        r.x += p.x; r.y += p.y; r.z += p.z; r.w += p.w;
    }
    ((float4*)out)[idx] = r;
}

// ---------------- launch ----------------
extern "C" void kernel_launch(void* const* d_in, const int* in_sizes, int n_in,
                              void* d_out, int out_size) {
    const float* x    = (const float*)d_in[0];
    const float* cw   = (const float*)d_in[1];
    const float* bias = (const float*)d_in[2];
    const float* gw   = (const float*)d_in[3];
    const float* uw   = (const float*)d_in[4];
    const float* dw   = (const float*)d_in[5];
    float* out = (float*)d_out;

    void* cntAddr = nullptr;
    cudaGetSymbolAddress(&cntAddr, g_cnt);
    cudaMemsetAsync(cntAddr, 0, NE * sizeof(int));

    router_kernel<<<T_TOK / 4, 128>>>(x, cw, bias);

    dim3 gb(IDIM / GU_BN, T_TOK / GU_BM, NE);
    gateup_kernel<<<gb, 256>>>(x, gw, uw);

    dim3 gd(H / DN_BN, T_TOK / DN_BM, NE);
    down_kernel<<<gd, 256>>>(dw);

    int n4 = T_TOK * (H / 4);
    combine_kernel<<<(n4 + 255) / 256, 256>>>(x, out);
}

// round 7
// speedup vs baseline: 3.4148x; 1.0658x over previous
#include <cuda_runtime.h>
#include <math.h>
#include <stdint.h>

#define T_TOK 4096
#define H     2048
#define IDIM  1024
#define NE    8
#define NTOT  12
#define CAP   4096
#define SCALE 1.5f

// ---------------- scratch (static device globals; no runtime allocation) ----------------
__device__ int   g_cnt[NE];
__device__ int   g_tok[NE * CAP];
__device__ float g_wt [NE * CAP];
__device__ int   g_dst[NE * CAP];
__device__ float g_zw [T_TOK];
__device__ int   g_mask[T_TOK];
__device__ float g_act [(size_t)NE * CAP * IDIM];     // expert-grouped activations
__device__ float g_pair[(size_t)T_TOK * 2 * H];       // per (token,k) down output

// ---------------- helpers ----------------
__device__ __forceinline__ void cp_async16(void* smem, const void* gmem) {
    uint32_t s = (uint32_t)__cvta_generic_to_shared(smem);
    asm volatile("cp.async.cg.shared.global [%0], [%1], 16;" :: "r"(s), "l"(gmem));
}
#define CP_COMMIT() asm volatile("cp.async.commit_group;")
#define CP_WAIT0()  asm volatile("cp.async.wait_group 0;")

// Raw fp32 bits fed as tf32 (hardware truncates mantissa).
__device__ __forceinline__ void mma_tf32(float c[4],
                                         uint32_t a0, uint32_t a1, uint32_t a2, uint32_t a3,
                                         uint32_t b0, uint32_t b1) {
    asm volatile(
        "mma.sync.aligned.m16n8k8.row.col.f32.tf32.tf32.f32 "
        "{%0,%1,%2,%3}, {%4,%5,%6,%7}, {%8,%9}, {%0,%1,%2,%3};\n"
        : "+f"(c[0]), "+f"(c[1]), "+f"(c[2]), "+f"(c[3])
        : "r"(a0), "r"(a1), "r"(a2), "r"(a3), "r"(b0), "r"(b1));
}

// ---------------- router: one warp per token ----------------
__global__ void router_kernel(const float* __restrict__ x,
                              const float* __restrict__ cw,
                              const float* __restrict__ bias) {
    int warp = threadIdx.x >> 5;
    int lane = threadIdx.x & 31;
    int t = blockIdx.x * 4 + warp;
    if (t >= T_TOK) return;
    const float* xr = x + (size_t)t * H;

    float acc[NTOT];
#pragma unroll
    for (int e = 0; e < NTOT; e++) acc[e] = 0.f;
    for (int h = lane; h < H; h += 32) {
        float xv = xr[h];
#pragma unroll
        for (int e = 0; e < NTOT; e++) acc[e] += xv * __ldg(&cw[e * H + h]);
    }
#pragma unroll
    for (int e = 0; e < NTOT; e++) {
#pragma unroll
        for (int off = 16; off; off >>= 1)
            acc[e] += __shfl_xor_sync(0xffffffffu, acc[e], off);
    }
    if (lane == 0) {
        float m = acc[0];
#pragma unroll
        for (int e = 1; e < NTOT; e++) m = fmaxf(m, acc[e]);
        float p[NTOT];
        float s = 0.f;
#pragma unroll
        for (int e = 0; e < NTOT; e++) { p[e] = expf(acc[e] - m); s += p[e]; }
        float inv = 1.f / s;
        float biased[NTOT];
#pragma unroll
        for (int e = 0; e < NTOT; e++) { p[e] *= inv; biased[e] = p[e] + bias[e]; }

        // top-2 of biased scores (lowest index wins ties, matching jax.lax.top_k)
        int i0 = 0;
#pragma unroll
        for (int e = 1; e < NTOT; e++) if (biased[e] > biased[i0]) i0 = e;
        int i1 = (i0 == 0) ? 1 : 0;
#pragma unroll
        for (int e = 0; e < NTOT; e++)
            if (e != i0 && biased[e] > biased[i1]) i1 = e;

        int sel[2] = { i0, i1 };
        float zw = 0.f;
        int mask = 0;
#pragma unroll
        for (int k = 0; k < 2; k++) {
            int e = sel[k];
            float w = p[e] * SCALE;       // weight uses UNBIASED prob
            if (e < NE) {
                int slot = atomicAdd(&g_cnt[e], 1);
                g_tok[e * CAP + slot] = t;
                g_wt [e * CAP + slot] = w;
                g_dst[e * CAP + slot] = t * 2 + k;
                mask |= (1 << k);
            } else {
                zw += w;
            }
        }
        g_zw[t]  = zw;
        g_mask[t] = mask;
    }
}

// ---------------- grouped gate+up tf32 GEMM, cp.async double-buffered ----------------
// Block tile: 128 slots x 64 inter, BK=16. 8 warps (4x2). Warp tile 32x32 for
// BOTH gate and up (shared A fragments).
#define GU_BM 128
#define GU_BN 64
#define GU_BK 16
#define GU_IT (H / GU_BK)
#define SMS 20   // smem k-stride (16 + 4 pad) -> conflict-free fragment LDS

__global__ __launch_bounds__(256, 2) void gateup_kernel(const float* __restrict__ x,
                                                        const float* __restrict__ gw,
                                                        const float* __restrict__ uw) {
    int e = blockIdx.z;
    int cnt = g_cnt[e];
    int t0 = blockIdx.y * GU_BM;
    if (t0 >= cnt) return;
    int i0 = blockIdx.x * GU_BN;

    __shared__ float SA[2][GU_BM][SMS];
    __shared__ float SG[2][GU_BN][SMS];
    __shared__ float SU[2][GU_BN][SMS];
    __shared__ int   toks[GU_BM];

    int tid  = threadIdx.x;
    int lane = tid & 31;
    int warp = tid >> 5;
    int wm = warp >> 1;       // 0..3
    int wn = warp & 1;        // 0..1
    int g = lane >> 2;        // 0..7
    int tg = lane & 3;        // 0..3

    if (tid < GU_BM) {
        int s = t0 + tid;
        toks[tid] = g_tok[e * CAP + ((s < cnt) ? s : 0)];
    }
    __syncthreads();

    int r0 = tid >> 2;        // 0..63
    int ch = (tid & 3) * 4;   // 0,4,8,12

    const float* a0 = x + (size_t)toks[r0] * H + ch;
    const float* a1 = x + (size_t)toks[r0 + 64] * H + ch;
    const float* gp = gw + (size_t)e * IDIM * H + (size_t)(i0 + r0) * H + ch;
    const float* up = uw + (size_t)e * IDIM * H + (size_t)(i0 + r0) * H + ch;

    float cg[2][4][4] = {};
    float cu[2][4][4] = {};

    // prologue: chunk 0 -> stage 0
    cp_async16(&SA[0][r0][ch], a0);
    cp_async16(&SA[0][r0 + 64][ch], a1);
    cp_async16(&SG[0][r0][ch], gp);
    cp_async16(&SU[0][r0][ch], up);
    CP_COMMIT();

    for (int k = 0; k < GU_IT; k++) {
        CP_WAIT0();
        __syncthreads();          // chunk k visible; all warps done with stage (k+1)&1

        int kn = k + 1;
        if (kn < GU_IT) {
            int st = kn & 1;
            int ko = kn * GU_BK;
            cp_async16(&SA[st][r0][ch], a0 + ko);
            cp_async16(&SA[st][r0 + 64][ch], a1 + ko);
            cp_async16(&SG[st][r0][ch], gp + ko);
            cp_async16(&SU[st][r0][ch], up + ko);
        }
        CP_COMMIT();

        int st = k & 1;
#pragma unroll
        for (int ks = 0; ks < GU_BK / 8; ks++) {
            int kb = ks * 8;
            uint32_t a[2][4];
#pragma unroll
            for (int mi = 0; mi < 2; mi++) {
                int rb = wm * 32 + mi * 16;
                a[mi][0] = __float_as_uint(SA[st][rb + g    ][kb + tg]);
                a[mi][1] = __float_as_uint(SA[st][rb + g + 8][kb + tg]);
                a[mi][2] = __float_as_uint(SA[st][rb + g    ][kb + tg + 4]);
                a[mi][3] = __float_as_uint(SA[st][rb + g + 8][kb + tg + 4]);
            }
#pragma unroll
            for (int ni = 0; ni < 4; ni++) {
                int nb = wn * 32 + ni * 8 + g;
                uint32_t bg0 = __float_as_uint(SG[st][nb][kb + tg]);
                uint32_t bg1 = __float_as_uint(SG[st][nb][kb + tg + 4]);
                uint32_t bu0 = __float_as_uint(SU[st][nb][kb + tg]);
                uint32_t bu1 = __float_as_uint(SU[st][nb][kb + tg + 4]);
#pragma unroll
                for (int mi = 0; mi < 2; mi++) {
                    mma_tf32(cg[mi][ni], a[mi][0], a[mi][1], a[mi][2], a[mi][3], bg0, bg1);
                    mma_tf32(cu[mi][ni], a[mi][0], a[mi][1], a[mi][2], a[mi][3], bu0, bu1);
                }
            }
        }
    }

    // epilogue: act = silu(gate) * up
#pragma unroll
    for (int mi = 0; mi < 2; mi++) {
        int rr = wm * 32 + mi * 16 + g;
        int srow0 = t0 + rr;
        int srow1 = srow0 + 8;
        float* row0 = g_act + ((size_t)e * CAP + srow0) * IDIM;
        float* row1 = g_act + ((size_t)e * CAP + srow1) * IDIM;
#pragma unroll
        for (int ni = 0; ni < 4; ni++) {
            int col = i0 + wn * 32 + ni * 8 + tg * 2;
            if (srow0 < cnt) {
                float g0 = cg[mi][ni][0], g1 = cg[mi][ni][1];
                float2 v;
                v.x = (g0 / (1.f + expf(-g0))) * cu[mi][ni][0];
                v.y = (g1 / (1.f + expf(-g1))) * cu[mi][ni][1];
                *(float2*)(row0 + col) = v;
            }
            if (srow1 < cnt) {
                float g2 = cg[mi][ni][2], g3 = cg[mi][ni][3];
                float2 v;
                v.x = (g2 / (1.f + expf(-g2))) * cu[mi][ni][2];
                v.y = (g3 / (1.f + expf(-g3))) * cu[mi][ni][3];
                *(float2*)(row1 + col) = v;
            }
        }
    }
}

// ---------------- grouped down tf32 GEMM, cp.async double-buffered ----------------
// Block tile: 128 slots x 128 H, BK=16. 8 warps (4x2). Warp tile 32x64.
#define DN_BM 128
#define DN_BN 128
#define DN_BK 16
#define DN_IT (IDIM / DN_BK)

__global__ __launch_bounds__(256, 2) void down_kernel(const float* __restrict__ dw) {
    int e = blockIdx.z;
    int cnt = g_cnt[e];
    int s0 = blockIdx.y * DN_BM;
    if (s0 >= cnt) return;
    int h0 = blockIdx.x * DN_BN;

    __shared__ float SA[2][DN_BM][SMS];
    __shared__ float SB[2][DN_BN][SMS];
    __shared__ float wts[DN_BM];
    __shared__ int   dsts[DN_BM];

    int tid  = threadIdx.x;
    int lane = tid & 31;
    int warp = tid >> 5;
    int wm = warp >> 1;      // 0..3
    int wn = warp & 1;       // 0..1
    int g = lane >> 2;
    int tg = lane & 3;

    if (tid < DN_BM) {
        int s = s0 + tid;
        int cs = (s < cnt) ? s : 0;
        wts[tid]  = g_wt [e * CAP + cs];
        dsts[tid] = g_dst[e * CAP + cs];
    }
    __syncthreads();

    int r0 = tid >> 2;       // 0..63
    int ch = (tid & 3) * 4;

    const float* a0 = g_act + ((size_t)e * CAP + s0 + r0) * IDIM + ch;
    const float* a1 = a0 + (size_t)64 * IDIM;
    const float* b0p = dw + (size_t)e * H * IDIM + (size_t)(h0 + r0) * IDIM + ch;
    const float* b1p = b0p + (size_t)64 * IDIM;

    float acc[2][8][4] = {};

    cp_async16(&SA[0][r0][ch], a0);
    cp_async16(&SA[0][r0 + 64][ch], a1);
    cp_async16(&SB[0][r0][ch], b0p);
    cp_async16(&SB[0][r0 + 64][ch], b1p);
    CP_COMMIT();

    for (int k = 0; k < DN_IT; k++) {
        CP_WAIT0();
        __syncthreads();

        int kn = k + 1;
        if (kn < DN_IT) {
            int st = kn & 1;
            int ko = kn * DN_BK;
            cp_async16(&SA[st][r0][ch], a0 + ko);
            cp_async16(&SA[st][r0 + 64][ch], a1 + ko);
            cp_async16(&SB[st][r0][ch], b0p + ko);
            cp_async16(&SB[st][r0 + 64][ch], b1p + ko);
        }
        CP_COMMIT();

        int st = k & 1;
#pragma unroll
        for (int ks = 0; ks < DN_BK / 8; ks++) {
            int kb = ks * 8;
            uint32_t a[2][4];
#pragma unroll
            for (int mi = 0; mi < 2; mi++) {
                int rb = wm * 32 + mi * 16;
                a[mi][0] = __float_as_uint(SA[st][rb + g    ][kb + tg]);
                a[mi][1] = __float_as_uint(SA[st][rb + g + 8][kb + tg]);
                a[mi][2] = __float_as_uint(SA[st][rb + g    ][kb + tg + 4]);
                a[mi][3] = __float_as_uint(SA[st][rb + g + 8][kb + tg + 4]);
            }
#pragma unroll
            for (int ni = 0; ni < 8; ni++) {
                int nb = wn * 64 + ni * 8 + g;
                uint32_t b0 = __float_as_uint(SB[st][nb][kb + tg]);
                uint32_t b1 = __float_as_uint(SB[st][nb][kb + tg + 4]);
#pragma unroll
                for (int mi = 0; mi < 2; mi++)
                    mma_tf32(acc[mi][ni], a[mi][0], a[mi][1], a[mi][2], a[mi][3], b0, b1);
            }
        }
    }

#pragma unroll
    for (int mi = 0; mi < 2; mi++) {
        int rr0 = wm * 32 + mi * 16 + g;
        int rr1 = rr0 + 8;
        int srow0 = s0 + rr0;
        int srow1 = s0 + rr1;
        float w0 = wts[rr0], w1 = wts[rr1];
        float* o0 = g_pair + (size_t)dsts[rr0] * H + h0;
        float* o1 = g_pair + (size_t)dsts[rr1] * H + h0;
#pragma unroll
        for (int ni = 0; ni < 8; ni++) {
            int col = wn * 64 + ni * 8 + tg * 2;
            if (srow0 < cnt) {
                float2 v = { acc[mi][ni][0] * w0, acc[mi][ni][1] * w0 };
                *(float2*)(o0 + col) = v;
            }
            if (srow1 < cnt) {
                float2 v = { acc[mi][ni][2] * w1, acc[mi][ni][3] * w1 };
                *(float2*)(o1 + col) = v;
            }
        }
    }
}

// ---------------- combine: out = x*zero_w + valid pair contributions ----------------
__global__ void combine_kernel(const float* __restrict__ x, float* __restrict__ out) {
    int idx = blockIdx.x * blockDim.x + threadIdx.x;
    if (idx >= T_TOK * (H / 4)) return;
    int t  = idx / (H / 4);
    int h4 = idx % (H / 4);
    float4 xv = ((const float4*)x)[idx];
    float zw = g_zw[t];
    int mask = g_mask[t];
    float4 r;
    r.x = xv.x * zw; r.y = xv.y * zw; r.z = xv.z * zw; r.w = xv.w * zw;
    if (mask & 1) {
        float4 p = ((const float4*)(g_pair + (size_t)(t * 2) * H))[h4];
        r.x += p.x; r.y += p.y; r.z += p.z; r.w += p.w;
    }
    if (mask & 2) {
        float4 p = ((const float4*)(g_pair + (size_t)(t * 2 + 1) * H))[h4];
        r.x += p.x; r.y += p.y; r.z += p.z; r.w += p.w;
    }
    ((float4*)out)[idx] = r;
}

// ---------------- launch ----------------
extern "C" void kernel_launch(void* const* d_in, const int* in_sizes, int n_in,
                              void* d_out, int out_size) {
    const float* x    = (const float*)d_in[0];
    const float* cw   = (const float*)d_in[1];
    const float* bias = (const float*)d_in[2];
    const float* gw   = (const float*)d_in[3];
    const float* uw   = (const float*)d_in[4];
    const float* dw   = (const float*)d_in[5];
    float* out = (float*)d_out;

    void* cntAddr = nullptr;
    cudaGetSymbolAddress(&cntAddr, g_cnt);
    cudaMemsetAsync(cntAddr, 0, NE * sizeof(int));

    router_kernel<<<T_TOK / 4, 128>>>(x, cw, bias);

    dim3 gb(IDIM / GU_BN, T_TOK / GU_BM, NE);
    gateup_kernel<<<gb, 256>>>(x, gw, uw);

    dim3 gd(H / DN_BN, T_TOK / DN_BM, NE);
    down_kernel<<<gd, 256>>>(dw);

    int n4 = T_TOK * (H / 4);
    combine_kernel<<<(n4 + 255) / 256, 256>>>(x, out);
}